// round 1
// baseline (speedup 1.0000x reference)
#include <cuda_runtime.h>
#include <cstdint>

#define L_DIM 1024
#define H_DIM 512
#define C_DIM 8
#define BC_DIM 16   // B*C

// Scratch for the two rank-1 vectors: a[bc][l], b[bc][m]
__device__ float g_av[BC_DIM * L_DIM];
__device__ float g_bv[BC_DIM * L_DIM];

// ---------------------------------------------------------------------------
// Kernel 1: per-row dot products
//   g_av[bc*L + l] = dot(start[bc,l,:], v1+v3)
//   g_bv[bc*L + m] = dot(end  [bc,m,:], v2-v3)
// One warp per row. grid=(16384/8, 2), block=256.
// ---------------------------------------------------------------------------
__global__ void vec_kernel(const float* __restrict__ start,
                           const float* __restrict__ endp,
                           const float* __restrict__ v) {
    int warp = threadIdx.x >> 5;
    int lane = threadIdx.x & 31;
    int row  = blockIdx.x * 8 + warp;          // [0, 16384)
    bool isA = (blockIdx.y == 0);
    const float* src = isA ? start : endp;
    const float4* r = (const float4*)(src + (size_t)row * H_DIM);

    float sum = 0.f;
#pragma unroll
    for (int it = 0; it < 4; it++) {
        int i = lane + it * 32;                // float4 index, [0,128)
        float4 x = r[i];
        int h = i * 4;
        float w0, w1, w2, w3;
        if (isA) {
            w0 = v[h + 0] + v[1024 + h + 0];
            w1 = v[h + 1] + v[1024 + h + 1];
            w2 = v[h + 2] + v[1024 + h + 2];
            w3 = v[h + 3] + v[1024 + h + 3];
        } else {
            w0 = v[512 + h + 0] - v[1024 + h + 0];
            w1 = v[512 + h + 1] - v[1024 + h + 1];
            w2 = v[512 + h + 2] - v[1024 + h + 2];
            w3 = v[512 + h + 3] - v[1024 + h + 3];
        }
        sum += x.x * w0 + x.y * w1 + x.z * w2 + x.w * w3;
    }
#pragma unroll
    for (int o = 16; o > 0; o >>= 1)
        sum += __shfl_down_sync(0xFFFFFFFFu, sum, o);
    if (lane == 0) {
        if (isA) g_av[row] = sum;
        else     g_bv[row] = sum;
    }
}

// ---------------------------------------------------------------------------
// Kernel 2: fused SGEMM  D[l,m] = (start*v4)[l,:] . end[m,:] + a[l] + b[m]
// Block tile 128x128, K-tile 8, 256 threads, 8x8 microtile (split 4+4).
// grid = (8, 8, 16) : (mtile, ltile, bc)
// ---------------------------------------------------------------------------
__global__ __launch_bounds__(256)
void gemm_kernel(const float* __restrict__ start,
                 const float* __restrict__ endp,
                 const float* __restrict__ v,
                 float* __restrict__ out) {
    const int bc = blockIdx.z;
    const int b  = bc >> 3;
    const int c  = bc & 7;
    const int ltile = blockIdx.y * 128;
    const int mtile = blockIdx.x * 128;

    const float* A  = start + (size_t)bc * L_DIM * H_DIM;
    const float* Bm = endp  + (size_t)bc * L_DIM * H_DIM;

    __shared__ float As[8][132];   // [k][row], pad 4 -> conflict-free stores/loads
    __shared__ float Bs[8][132];
    __shared__ float v4s[H_DIM];

    const int tid = threadIdx.x;
    for (int i = tid; i < H_DIM; i += 256) v4s[i] = v[1536 + i];

    // global load mapping: 128 rows x 8 k per tile; thread -> (row, 4 k's)
    const int arow = tid >> 1;
    const int acol = (tid & 1) * 4;
    const float* Aload = A  + (size_t)(ltile + arow) * H_DIM + acol;
    const float* Bload = Bm + (size_t)(mtile + arow) * H_DIM + acol;

    const int tx = tid & 15;    // 16 cols of threads
    const int ty = tid >> 4;    // 16 rows of threads

    float acc[8][8];
#pragma unroll
    for (int i = 0; i < 8; i++)
#pragma unroll
        for (int j = 0; j < 8; j++) acc[i][j] = 0.f;

    float4 pa = *(const float4*)Aload;
    float4 pb = *(const float4*)Bload;

    __syncthreads();   // v4s ready

    for (int kt = 0; kt < H_DIM; kt += 8) {
        // store tile (apply v4 to A here)
        As[acol + 0][arow] = pa.x * v4s[kt + acol + 0];
        As[acol + 1][arow] = pa.y * v4s[kt + acol + 1];
        As[acol + 2][arow] = pa.z * v4s[kt + acol + 2];
        As[acol + 3][arow] = pa.w * v4s[kt + acol + 3];
        Bs[acol + 0][arow] = pb.x;
        Bs[acol + 1][arow] = pb.y;
        Bs[acol + 2][arow] = pb.z;
        Bs[acol + 3][arow] = pb.w;
        __syncthreads();

        if (kt + 8 < H_DIM) {
            pa = *(const float4*)(Aload + kt + 8);
            pb = *(const float4*)(Bload + kt + 8);
        }

#pragma unroll
        for (int k = 0; k < 8; k++) {
            float4 a0 = *(const float4*)&As[k][ty * 4];
            float4 a1 = *(const float4*)&As[k][64 + ty * 4];
            float4 b0 = *(const float4*)&Bs[k][tx * 4];
            float4 b1 = *(const float4*)&Bs[k][64 + tx * 4];
            float ar[8] = {a0.x, a0.y, a0.z, a0.w, a1.x, a1.y, a1.z, a1.w};
            float br[8] = {b0.x, b0.y, b0.z, b0.w, b1.x, b1.y, b1.z, b1.w};
#pragma unroll
            for (int ii = 0; ii < 8; ii++)
#pragma unroll
                for (int jj = 0; jj < 8; jj++)
                    acc[ii][jj] += ar[ii] * br[jj];
        }
        __syncthreads();
    }

    // epilogue: add rank-1 vectors, write transposed output out[b,l,m,c]
    int rows[8], cols[8];
#pragma unroll
    for (int q = 0; q < 4; q++) {
        rows[q]     = ty * 4 + q;
        rows[q + 4] = 64 + ty * 4 + q;
        cols[q]     = tx * 4 + q;
        cols[q + 4] = 64 + tx * 4 + q;
    }
    float av[8], bv[8];
#pragma unroll
    for (int q = 0; q < 8; q++) {
        av[q] = g_av[bc * L_DIM + ltile + rows[q]];
        bv[q] = g_bv[bc * L_DIM + mtile + cols[q]];
    }

#pragma unroll
    for (int ii = 0; ii < 8; ii++) {
        size_t obase = (((size_t)b * L_DIM + (ltile + rows[ii])) * L_DIM + mtile) * C_DIM + c;
#pragma unroll
        for (int jj = 0; jj < 8; jj++) {
            out[obase + (size_t)cols[jj] * C_DIM] = acc[ii][jj] + av[ii] + bv[jj];
        }
    }
}

extern "C" void kernel_launch(void* const* d_in, const int* in_sizes, int n_in,
                              void* d_out, int out_size) {
    const float* start = (const float*)d_in[0];
    const float* endp  = (const float*)d_in[1];
    const float* v     = (const float*)d_in[2];
    float* out = (float*)d_out;

    vec_kernel<<<dim3(BC_DIM * L_DIM / 8, 2), 256>>>(start, endp, v);
    gemm_kernel<<<dim3(8, 8, BC_DIM), 256>>>(start, endp, v, out);
}

// round 3
// speedup vs baseline: 2.2299x; 2.2299x over previous
#include <cuda_runtime.h>
#include <cstdint>

#define L_DIM 1024
#define H_DIM 512
#define C_DIM 8
#define BC_DIM 16

// GEMM tiling
#define BM 128
#define BN 128
#define KC 32                 // k per stage = 4 k8-tiles
#define STAGES 3
#define KSTEPS (H_DIM / KC)   // 16
#define A_STG_FLOATS 4096     // 8 I-tiles * 4 KK * 128
#define B_STG_FLOATS 4096     // 16 J-tiles * 4 KK * 64
#define STG_FLOATS   8192
#define SMEM_DYN (STAGES * STG_FLOATS * 4)   // 96 KB

// ---- static device scratch ----
__device__ float g_av[BC_DIM * L_DIM];
__device__ float g_bv[BC_DIM * L_DIM];
__device__ float4 g_pa[(size_t)BC_DIM * 64 * 64 * 32];        // [bc][I][KK][lane] (4 floats)
__device__ float2 g_pb[(size_t)BC_DIM * 128 * 64 * 32];       // [bc][J][KK][lane] (2 floats)
__device__ float  g_dm[(size_t)BC_DIM * L_DIM * L_DIM];       // [bc][l][m]

// ---------------- helpers ----------------
__device__ __forceinline__ uint32_t cvt_tf32(float x) {
    uint32_t u;
    asm("cvt.rna.tf32.f32 %0, %1;" : "=r"(u) : "f"(x));
    return u;
}
#define CP_ASYNC16(saddr, gaddr) \
    asm volatile("cp.async.cg.shared.global [%0], [%1], 16;" :: "r"(saddr), "l"(gaddr) : "memory")
#define CP_COMMIT() asm volatile("cp.async.commit_group;" ::: "memory")
#define CP_WAIT1()  asm volatile("cp.async.wait_group 1;" ::: "memory")

__device__ __forceinline__ uint32_t smem_u32(const void* p) {
    uint32_t a;
    asm("{ .reg .u64 t; cvta.to.shared.u64 t, %1; cvt.u32.u64 %0, t; }" : "=r"(a) : "l"(p));
    return a;
}
__device__ __forceinline__ void mma_tf32(float* d, const uint32_t* a, const uint32_t* b) {
    asm volatile(
        "mma.sync.aligned.m16n8k8.row.col.f32.tf32.tf32.f32 "
        "{%0,%1,%2,%3}, {%4,%5,%6,%7}, {%8,%9}, {%0,%1,%2,%3};"
        : "+f"(d[0]), "+f"(d[1]), "+f"(d[2]), "+f"(d[3])
        : "r"(a[0]), "r"(a[1]), "r"(a[2]), "r"(a[3]), "r"(b[0]), "r"(b[1]));
}

// ---------------------------------------------------------------------------
// Kernel 1: per-row dot products (validated in R1)
// ---------------------------------------------------------------------------
__global__ void vec_kernel(const float* __restrict__ start,
                           const float* __restrict__ endp,
                           const float* __restrict__ v) {
    int warp = threadIdx.x >> 5, lane = threadIdx.x & 31;
    int row = blockIdx.x * 8 + warp;
    bool isA = (blockIdx.y == 0);
    const float* src = isA ? start : endp;
    const float4* r = (const float4*)(src + (size_t)row * H_DIM);
    float sum = 0.f;
#pragma unroll
    for (int it = 0; it < 4; it++) {
        int i = lane + it * 32;
        float4 x = r[i];
        int h = i * 4;
        float w0, w1, w2, w3;
        if (isA) {
            w0 = v[h+0] + v[1024+h+0]; w1 = v[h+1] + v[1024+h+1];
            w2 = v[h+2] + v[1024+h+2]; w3 = v[h+3] + v[1024+h+3];
        } else {
            w0 = v[512+h+0] - v[1024+h+0]; w1 = v[512+h+1] - v[1024+h+1];
            w2 = v[512+h+2] - v[1024+h+2]; w3 = v[512+h+3] - v[1024+h+3];
        }
        sum += x.x*w0 + x.y*w1 + x.z*w2 + x.w*w3;
    }
#pragma unroll
    for (int o = 16; o > 0; o >>= 1) sum += __shfl_down_sync(0xFFFFFFFFu, sum, o);
    if (lane == 0) { if (isA) g_av[row] = sum; else g_bv[row] = sum; }
}

// ---------------------------------------------------------------------------
// Kernel 2a: pack A = tf32(start * v4) in fragment layout
//   g_pa[bc][I][KK][lane] = {A(16I+g, 8KK+t), A(16I+g+8, 8KK+t),
//                            A(16I+g, 8KK+t+4), A(16I+g+8, 8KK+t+4)} * v4
// grid (64 I, 16 bc), 256 threads (warp w -> KK = w*8 .. w*8+7)
// ---------------------------------------------------------------------------
__global__ void pack_a_kernel(const float* __restrict__ start, const float* __restrict__ v) {
    const int I = blockIdx.x, bc = blockIdx.y;
    const int w = threadIdx.x >> 5, lane = threadIdx.x & 31;
    const int g = lane >> 2, t = lane & 3;
    const float* A = start + (size_t)bc * L_DIM * H_DIM;
    const float* v4 = v + 1536;
    const int r0 = I * 16 + g;
    float4* outp = g_pa + ((size_t)(bc * 64 + I) * 64) * 32;
#pragma unroll
    for (int it = 0; it < 8; it++) {
        int KK = w * 8 + it;
        int c0 = KK * 8 + t;
        float s0 = v4[c0], s1 = v4[c0 + 4];
        float f0 = A[(size_t)r0 * H_DIM + c0] * s0;
        float f1 = A[(size_t)(r0 + 8) * H_DIM + c0] * s0;
        float f2 = A[(size_t)r0 * H_DIM + c0 + 4] * s1;
        float f3 = A[(size_t)(r0 + 8) * H_DIM + c0 + 4] * s1;
        float4 o;
        o.x = __uint_as_float(cvt_tf32(f0));
        o.y = __uint_as_float(cvt_tf32(f1));
        o.z = __uint_as_float(cvt_tf32(f2));
        o.w = __uint_as_float(cvt_tf32(f3));
        outp[(size_t)KK * 32 + lane] = o;
    }
}

// ---------------------------------------------------------------------------
// Kernel 2b: pack B = tf32(end) in fragment layout
//   g_pb[bc][J][KK][lane] = {B(8J+g, 8KK+t), B(8J+g, 8KK+t+4)}
// grid (16 Jb, 16 bc), 256 threads (warp w -> J = Jb*8 + w, loop KK)
// ---------------------------------------------------------------------------
__global__ void pack_b_kernel(const float* __restrict__ endp) {
    const int Jb = blockIdx.x, bc = blockIdx.y;
    const int w = threadIdx.x >> 5, lane = threadIdx.x & 31;
    const int g = lane >> 2, t = lane & 3;
    const int J = Jb * 8 + w;
    const float* B = endp + (size_t)bc * L_DIM * H_DIM + (size_t)(J * 8 + g) * H_DIM;
    float2* outp = g_pb + ((size_t)(bc * 128 + J) * 64) * 32;
#pragma unroll
    for (int KK = 0; KK < 64; KK++) {
        int k0 = KK * 8 + t;
        float2 o;
        o.x = __uint_as_float(cvt_tf32(B[k0]));
        o.y = __uint_as_float(cvt_tf32(B[k0 + 4]));
        outp[(size_t)KK * 32 + lane] = o;
    }
}

// ---------------------------------------------------------------------------
// Kernel 3: TF32 mma.sync GEMM, CTA tile 128x128, K=512
//   dm[bc][l][m] = sum_k pa . pb + av[l] + bv[m]
// grid (8, 8, 16), 256 threads (2x4 warps, warp tile 64x32)
// ---------------------------------------------------------------------------
__global__ __launch_bounds__(256, 2)
void gemm_mma(float* __restrict__ dm) {
    extern __shared__ __align__(16) float smem[];
    __shared__ float av_s[BM], bv_s[BN];

    const int tid = threadIdx.x;
    const int bc = blockIdx.z;
    const int ltile = blockIdx.y * BM;
    const int mtile = blockIdx.x * BN;
    const int Ib = blockIdx.y * 8;     // first 16-row tile
    const int Jb = blockIdx.x * 16;    // first 8-col tile

    if (tid < BM) av_s[tid] = g_av[bc * L_DIM + ltile + tid];
    else          bv_s[tid - BM] = g_bv[bc * L_DIM + mtile + (tid - BM)];

    const uint32_t smem_b = smem_u32(smem);

    // --- cp.async fill mapping ---
    const int bA = tid >> 3;                 // 0..31 : (I_loc*4 + KK_loc)
    const int qA = tid & 7;                  // 16-float sub-chunk
    const int bB = tid >> 2;                 // 0..63 : (J_loc*4 + KK_loc)
    const int qB = tid & 3;
    const float* paBase = (const float*)g_pa +
        (((size_t)(bc * 64 + Ib + (bA >> 2)) * 64 + (bA & 3)) * 32) * 4 + qA * 16;
    const float* pbBase = (const float*)g_pb +
        (((size_t)(bc * 128 + Jb + (bB >> 2)) * 64 + (bB & 3)) * 32) * 2 + qB * 16;
    const uint32_t sA = smem_b + (bA * 128 + qA * 16) * 4;
    const uint32_t sB = smem_b + (A_STG_FLOATS + bB * 64 + qB * 16) * 4;

#define FILL(S, BUF) do {                                                      \
        const float* _pa = paBase + (size_t)(S) * 4 * 128;                     \
        const float* _pb = pbBase + (size_t)(S) * 4 * 64;                      \
        uint32_t _o = (BUF) * STG_FLOATS * 4;                                  \
        CP_ASYNC16(sA + _o,      _pa);      CP_ASYNC16(sA + _o + 16, _pa + 4); \
        CP_ASYNC16(sA + _o + 32, _pa + 8);  CP_ASYNC16(sA + _o + 48, _pa + 12);\
        CP_ASYNC16(sB + _o,      _pb);      CP_ASYNC16(sB + _o + 16, _pb + 4); \
        CP_ASYNC16(sB + _o + 32, _pb + 8);  CP_ASYNC16(sB + _o + 48, _pb + 12);\
    } while (0)

    FILL(0, 0); CP_COMMIT();
    FILL(1, 1); CP_COMMIT();

    const int wid = tid >> 5, lane = tid & 31;
    const int warp_m = wid >> 2, warp_n = wid & 3;
    const int g = lane >> 2, t = lane & 3;

    float d[4][4][4];
#pragma unroll
    for (int i = 0; i < 4; i++)
#pragma unroll
        for (int j = 0; j < 4; j++)
#pragma unroll
            for (int q = 0; q < 4; q++) d[i][j][q] = 0.f;

    const uint32_t* As = (const uint32_t*)smem;
    const uint32_t* Bs = (const uint32_t*)(smem + A_STG_FLOATS);

    for (int s = 0; s < KSTEPS; s++) {
        const int buf = s % STAGES;
        CP_WAIT1();
        __syncthreads();
        if (s + 2 < KSTEPS) FILL(s + 2, (s + 2) % STAGES);
        CP_COMMIT();

        const uint32_t* Ab = As + buf * STG_FLOATS;
        const uint32_t* Bb = Bs + buf * STG_FLOATS;
#pragma unroll
        for (int kk = 0; kk < 4; kk++) {
            uint32_t a[4][4], b[4][2];
#pragma unroll
            for (int i = 0; i < 4; i++) {
                const uint4 va = *(const uint4*)&Ab[((warp_m * 4 + i) * 4 + kk) * 128 + lane * 4];
                a[i][0] = va.x; a[i][1] = va.y; a[i][2] = va.z; a[i][3] = va.w;
            }
#pragma unroll
            for (int j = 0; j < 4; j++) {
                const uint2 vb = *(const uint2*)&Bb[((warp_n * 4 + j) * 4 + kk) * 64 + lane * 2];
                b[j][0] = vb.x; b[j][1] = vb.y;
            }
#pragma unroll
            for (int i = 0; i < 4; i++)
#pragma unroll
                for (int j = 0; j < 4; j++)
                    mma_tf32(d[i][j], a[i], b[j]);
        }
        __syncthreads();
    }

    // epilogue: add rank-1 terms, write dm rows
#pragma unroll
    for (int i = 0; i < 4; i++) {
        const int lr0 = warp_m * 64 + i * 16 + g;
        const float av0 = av_s[lr0], av1 = av_s[lr0 + 8];
        float* row0 = dm + ((size_t)bc * L_DIM + ltile + lr0) * L_DIM + mtile;
        float* row1 = row0 + (size_t)8 * L_DIM;
#pragma unroll
        for (int j = 0; j < 4; j++) {
            const int lc = warp_n * 32 + j * 8 + t * 2;
            const float bv0 = bv_s[lc], bv1 = bv_s[lc + 1];
            float2 o0, o1;
            o0.x = d[i][j][0] + av0 + bv0;
            o0.y = d[i][j][1] + av0 + bv1;
            o1.x = d[i][j][2] + av1 + bv0;
            o1.y = d[i][j][3] + av1 + bv1;
            *(float2*)(row0 + lc) = o0;
            *(float2*)(row1 + lc) = o1;
        }
    }
}

// ---------------------------------------------------------------------------
// Kernel 4: transpose  out[b,l,m,c] = g_dm[b*8+c][l][m]
// ---------------------------------------------------------------------------
__global__ void transpose_kernel(const float* __restrict__ dm, float* __restrict__ out) {
    size_t idx = (size_t)blockIdx.x * blockDim.x + threadIdx.x;
    int m = (int)(idx & 1023);
    int l = (int)((idx >> 10) & 1023);
    int b = (int)(idx >> 20);
    const float* base = dm + ((size_t)b * 8) * 1048576 + (size_t)l * 1024 + m;
    float4 o0, o1;
    o0.x = base[0];
    o0.y = base[1 * 1048576];
    o0.z = base[2 * 1048576];
    o0.w = base[3 * 1048576];
    o1.x = base[4 * 1048576];
    o1.y = base[5 * 1048576];
    o1.z = base[6 * 1048576];
    o1.w = base[7 * 1048576];
    float4* op = (float4*)(out + idx * 8);
    op[0] = o0; op[1] = o1;
}

extern "C" void kernel_launch(void* const* d_in, const int* in_sizes, int n_in,
                              void* d_out, int out_size) {
    const float* start = (const float*)d_in[0];
    const float* endp  = (const float*)d_in[1];
    const float* v     = (const float*)d_in[2];
    float* out = (float*)d_out;

    static bool attr_set = false;
    if (!attr_set) {
        cudaFuncSetAttribute(gemm_mma, cudaFuncAttributeMaxDynamicSharedMemorySize, SMEM_DYN);
        attr_set = true;
    }

    float* dm;
    cudaGetSymbolAddress((void**)&dm, g_dm);

    vec_kernel<<<dim3(BC_DIM * L_DIM / 8, 2), 256>>>(start, endp, v);
    pack_a_kernel<<<dim3(64, BC_DIM), 256>>>(start, v);
    pack_b_kernel<<<dim3(16, BC_DIM), 256>>>(endp);
    gemm_mma<<<dim3(8, 8, BC_DIM), 256, SMEM_DYN>>>(dm);
    transpose_kernel<<<(2u * 1024 * 1024) / 256, 256>>>(dm, out);
}

// round 4
// speedup vs baseline: 2.3777x; 1.0663x over previous
#include <cuda_runtime.h>
#include <cstdint>

#define L_DIM 1024
#define H_DIM 512
#define C_DIM 8
#define BC_DIM 16

// GEMM tiling
#define BM 128
#define BN 128
#define KC 32                 // k per stage = 4 k8-tiles
#define STAGES 3
#define KSTEPS (H_DIM / KC)   // 16
#define A_STG_FLOATS 4096
#define B_STG_FLOATS 4096
#define STG_FLOATS   8192
#define SMEM_DYN (STAGES * STG_FLOATS * 4)   // 96 KB

// ---- static device scratch ----
__device__ float g_av[BC_DIM * L_DIM];
__device__ float g_bv[BC_DIM * L_DIM];
__device__ float4 g_pa[(size_t)BC_DIM * 64 * 64 * 32];        // [bc][I][KK][lane]
__device__ float2 g_pb[(size_t)BC_DIM * 128 * 64 * 32];       // [bc][J][KK][lane]
__device__ float  g_dm[(size_t)BC_DIM * L_DIM * L_DIM];       // [bc][l][m]

// ---------------- helpers ----------------
__device__ __forceinline__ uint32_t cvt_tf32(float x) {
    uint32_t u;
    asm("cvt.rna.tf32.f32 %0, %1;" : "=r"(u) : "f"(x));
    return u;
}
#define CP_ASYNC16(saddr, gaddr) \
    asm volatile("cp.async.cg.shared.global [%0], [%1], 16;" :: "r"(saddr), "l"(gaddr) : "memory")
#define CP_COMMIT() asm volatile("cp.async.commit_group;" ::: "memory")
#define CP_WAIT1()  asm volatile("cp.async.wait_group 1;" ::: "memory")

__device__ __forceinline__ uint32_t smem_u32(const void* p) {
    uint32_t a;
    asm("{ .reg .u64 t; cvta.to.shared.u64 t, %1; cvt.u32.u64 %0, t; }" : "=r"(a) : "l"(p));
    return a;
}
__device__ __forceinline__ void mma_tf32(float* d, const uint32_t* a, const uint32_t* b) {
    asm volatile(
        "mma.sync.aligned.m16n8k8.row.col.f32.tf32.tf32.f32 "
        "{%0,%1,%2,%3}, {%4,%5,%6,%7}, {%8,%9}, {%0,%1,%2,%3};"
        : "+f"(d[0]), "+f"(d[1]), "+f"(d[2]), "+f"(d[3])
        : "r"(a[0]), "r"(a[1]), "r"(a[2]), "r"(a[3]), "r"(b[0]), "r"(b[1]));
}

// ---------------------------------------------------------------------------
// Kernel 1a: pack A = tf32(start * v4) in fragment layout + fused row dots
//   g_av[r] = dot(start_r, v1+v3)
// grid (64 I, 16 bc), 256 threads (warp w -> KK = w*8 .. w*8+7)
// ---------------------------------------------------------------------------
__global__ void pack_a_kernel(const float* __restrict__ start, const float* __restrict__ v) {
    __shared__ float dots[16];
    const int I = blockIdx.x, bc = blockIdx.y;
    const int tid = threadIdx.x;
    if (tid < 16) dots[tid] = 0.f;
    __syncthreads();

    const int w = tid >> 5, lane = tid & 31;
    const int g = lane >> 2, t = lane & 3;
    const float* A = start + (size_t)bc * L_DIM * H_DIM;
    const float* v4 = v + 1536;
    const int r0 = I * 16 + g;
    float4* outp = g_pa + ((size_t)(bc * 64 + I) * 64) * 32;

    float d0 = 0.f, d1 = 0.f;
#pragma unroll
    for (int it = 0; it < 8; it++) {
        int KK = w * 8 + it;
        int c0 = KK * 8 + t;
        float a00 = A[(size_t)r0 * H_DIM + c0];
        float a10 = A[(size_t)(r0 + 8) * H_DIM + c0];
        float a01 = A[(size_t)r0 * H_DIM + c0 + 4];
        float a11 = A[(size_t)(r0 + 8) * H_DIM + c0 + 4];
        float w0 = v[c0] + v[1024 + c0];
        float w1 = v[c0 + 4] + v[1024 + c0 + 4];
        d0 += a00 * w0 + a01 * w1;
        d1 += a10 * w0 + a11 * w1;
        float s0 = v4[c0], s1 = v4[c0 + 4];
        float4 o;
        o.x = __uint_as_float(cvt_tf32(a00 * s0));
        o.y = __uint_as_float(cvt_tf32(a10 * s0));
        o.z = __uint_as_float(cvt_tf32(a01 * s1));
        o.w = __uint_as_float(cvt_tf32(a11 * s1));
        outp[(size_t)KK * 32 + lane] = o;
    }
    atomicAdd(&dots[g], d0);
    atomicAdd(&dots[g + 8], d1);
    __syncthreads();
    if (tid < 16) g_av[bc * L_DIM + I * 16 + tid] = dots[tid];
}

// ---------------------------------------------------------------------------
// Kernel 1b: pack B = tf32(end) in fragment layout + fused row dots
//   g_bv[r] = dot(end_r, v2-v3)
// grid (16 Jb, 16 bc), 256 threads (warp w -> J = Jb*8 + w)
// ---------------------------------------------------------------------------
__global__ void pack_b_kernel(const float* __restrict__ endp, const float* __restrict__ v) {
    const int Jb = blockIdx.x, bc = blockIdx.y;
    const int w = threadIdx.x >> 5, lane = threadIdx.x & 31;
    const int g = lane >> 2, t = lane & 3;
    const int J = Jb * 8 + w;
    const int row = J * 8 + g;
    const float* B = endp + (size_t)bc * L_DIM * H_DIM + (size_t)row * H_DIM;
    float2* outp = g_pb + ((size_t)(bc * 128 + J) * 64) * 32;

    float d = 0.f;
#pragma unroll
    for (int KK = 0; KK < 64; KK++) {
        int k0 = KK * 8 + t;
        float b0 = B[k0], b1 = B[k0 + 4];
        d += b0 * (v[512 + k0] - v[1024 + k0]) +
             b1 * (v[512 + k0 + 4] - v[1024 + k0 + 4]);
        float2 o;
        o.x = __uint_as_float(cvt_tf32(b0));
        o.y = __uint_as_float(cvt_tf32(b1));
        outp[(size_t)KK * 32 + lane] = o;
    }
    d += __shfl_xor_sync(0xFFFFFFFFu, d, 1);
    d += __shfl_xor_sync(0xFFFFFFFFu, d, 2);
    if (t == 0) g_bv[bc * L_DIM + row] = d;
}

// ---------------------------------------------------------------------------
// Kernel 2: TF32 mma.sync GEMM, CTA tile 128x128, K=512
// grid (8, 8, 16), 256 threads (2x4 warps, warp tile 64x32)
// Register double-buffered fragments; one barrier per stage.
// ---------------------------------------------------------------------------
__global__ __launch_bounds__(256, 2)
void gemm_mma(float* __restrict__ dm) {
    extern __shared__ __align__(16) float smem[];
    __shared__ float av_s[BM], bv_s[BN];

    const int tid = threadIdx.x;
    const int bc = blockIdx.z;
    const int ltile = blockIdx.y * BM;
    const int mtile = blockIdx.x * BN;
    const int Ib = blockIdx.y * 8;
    const int Jb = blockIdx.x * 16;

    if (tid < BM) av_s[tid] = g_av[bc * L_DIM + ltile + tid];
    else          bv_s[tid - BM] = g_bv[bc * L_DIM + mtile + (tid - BM)];

    const uint32_t smem_b = smem_u32(smem);

    const int bA = tid >> 3;
    const int qA = tid & 7;
    const int bB = tid >> 2;
    const int qB = tid & 3;
    const float* paBase = (const float*)g_pa +
        (((size_t)(bc * 64 + Ib + (bA >> 2)) * 64 + (bA & 3)) * 32) * 4 + qA * 16;
    const float* pbBase = (const float*)g_pb +
        (((size_t)(bc * 128 + Jb + (bB >> 2)) * 64 + (bB & 3)) * 32) * 2 + qB * 16;
    const uint32_t sA = smem_b + (bA * 128 + qA * 16) * 4;
    const uint32_t sB = smem_b + (A_STG_FLOATS + bB * 64 + qB * 16) * 4;

#define FILL(S, BUF) do {                                                      \
        const float* _pa = paBase + (size_t)(S) * 4 * 128;                     \
        const float* _pb = pbBase + (size_t)(S) * 4 * 64;                      \
        uint32_t _o = (BUF) * STG_FLOATS * 4;                                  \
        CP_ASYNC16(sA + _o,      _pa);      CP_ASYNC16(sA + _o + 16, _pa + 4); \
        CP_ASYNC16(sA + _o + 32, _pa + 8);  CP_ASYNC16(sA + _o + 48, _pa + 12);\
        CP_ASYNC16(sB + _o,      _pb);      CP_ASYNC16(sB + _o + 16, _pb + 4); \
        CP_ASYNC16(sB + _o + 32, _pb + 8);  CP_ASYNC16(sB + _o + 48, _pb + 12);\
    } while (0)

    FILL(0, 0); CP_COMMIT();
    FILL(1, 1); CP_COMMIT();

    const int wid = tid >> 5, lane = tid & 31;
    const int warp_m = wid >> 2, warp_n = wid & 3;
    const int g = lane >> 2, t = lane & 3;

    float d[4][4][4];
#pragma unroll
    for (int i = 0; i < 4; i++)
#pragma unroll
        for (int j = 0; j < 4; j++)
#pragma unroll
            for (int q = 0; q < 4; q++) d[i][j][q] = 0.f;

    const uint32_t* As = (const uint32_t*)smem;
    const uint32_t* Bs = (const uint32_t*)(smem + A_STG_FLOATS);

    uint32_t afr[2][4][4];
    uint32_t bfr[2][4][2];

#define LOADFRAG(DST, KK, Ab, Bb) do {                                          \
        _Pragma("unroll")                                                       \
        for (int _i = 0; _i < 4; _i++) {                                        \
            const uint4 _va = *(const uint4*)&(Ab)[((warp_m * 4 + _i) * 4 + (KK)) * 128 + lane * 4]; \
            afr[DST][_i][0] = _va.x; afr[DST][_i][1] = _va.y;                   \
            afr[DST][_i][2] = _va.z; afr[DST][_i][3] = _va.w;                   \
        }                                                                       \
        _Pragma("unroll")                                                       \
        for (int _j = 0; _j < 4; _j++) {                                        \
            const uint2 _vb = *(const uint2*)&(Bb)[((warp_n * 4 + _j) * 4 + (KK)) * 64 + lane * 2]; \
            bfr[DST][_j][0] = _vb.x; bfr[DST][_j][1] = _vb.y;                   \
        } } while (0)

    for (int s = 0; s < KSTEPS; s++) {
        const int buf = s % STAGES;
        CP_WAIT1();
        __syncthreads();
        if (s + 2 < KSTEPS) FILL(s + 2, (s + 2) % STAGES);
        CP_COMMIT();

        const uint32_t* Ab = As + buf * STG_FLOATS;
        const uint32_t* Bb = Bs + buf * STG_FLOATS;

        LOADFRAG(0, 0, Ab, Bb);
#pragma unroll
        for (int kk = 0; kk < 4; kk++) {
            const int cur = kk & 1;
            if (kk < 3) LOADFRAG(cur ^ 1, kk + 1, Ab, Bb);
#pragma unroll
            for (int i = 0; i < 4; i++)
#pragma unroll
                for (int j = 0; j < 4; j++)
                    mma_tf32(d[i][j], afr[cur][i], bfr[cur][j]);
        }
    }

    // epilogue
#pragma unroll
    for (int i = 0; i < 4; i++) {
        const int lr0 = warp_m * 64 + i * 16 + g;
        const float av0 = av_s[lr0], av1 = av_s[lr0 + 8];
        float* row0 = dm + ((size_t)bc * L_DIM + ltile + lr0) * L_DIM + mtile;
        float* row1 = row0 + (size_t)8 * L_DIM;
#pragma unroll
        for (int j = 0; j < 4; j++) {
            const int lc = warp_n * 32 + j * 8 + t * 2;
            const float bv0 = bv_s[lc], bv1 = bv_s[lc + 1];
            float2 o0, o1;
            o0.x = d[i][j][0] + av0 + bv0;
            o0.y = d[i][j][1] + av0 + bv1;
            o1.x = d[i][j][2] + av1 + bv0;
            o1.y = d[i][j][3] + av1 + bv1;
            *(float2*)(row0 + lc) = o0;
            *(float2*)(row1 + lc) = o1;
        }
    }
}

// ---------------------------------------------------------------------------
// Kernel 3: transpose  out[b,l,m,c] = g_dm[b*8+c][l][m]
// ---------------------------------------------------------------------------
__global__ void transpose_kernel(const float* __restrict__ dm, float* __restrict__ out) {
    size_t idx = (size_t)blockIdx.x * blockDim.x + threadIdx.x;
    int m = (int)(idx & 1023);
    int l = (int)((idx >> 10) & 1023);
    int b = (int)(idx >> 20);
    const float* base = dm + ((size_t)b * 8) * 1048576 + (size_t)l * 1024 + m;
    float4 o0, o1;
    o0.x = base[0];
    o0.y = base[1 * 1048576];
    o0.z = base[2 * 1048576];
    o0.w = base[3 * 1048576];
    o1.x = base[4 * 1048576];
    o1.y = base[5 * 1048576];
    o1.z = base[6 * 1048576];
    o1.w = base[7 * 1048576];
    float4* op = (float4*)(out + idx * 8);
    op[0] = o0; op[1] = o1;
}

extern "C" void kernel_launch(void* const* d_in, const int* in_sizes, int n_in,
                              void* d_out, int out_size) {
    const float* start = (const float*)d_in[0];
    const float* endp  = (const float*)d_in[1];
    const float* v     = (const float*)d_in[2];
    float* out = (float*)d_out;

    static bool attr_set = false;
    if (!attr_set) {
        cudaFuncSetAttribute(gemm_mma, cudaFuncAttributeMaxDynamicSharedMemorySize, SMEM_DYN);
        attr_set = true;
    }

    float* dm;
    cudaGetSymbolAddress((void**)&dm, g_dm);

    pack_a_kernel<<<dim3(64, BC_DIM), 256>>>(start, v);
    pack_b_kernel<<<dim3(16, BC_DIM), 256>>>(endp, v);
    gemm_mma<<<dim3(8, 8, BC_DIM), 256, SMEM_DYN>>>(dm);
    transpose_kernel<<<(2u * 1024 * 1024) / 256, 256>>>(dm, out);
}